// round 10
// baseline (speedup 1.0000x reference)
#include <cuda_runtime.h>
#include <cuda_bf16.h>
#include <math.h>
#include <stdint.h>

#define B 4
#define T 2048
#define C 1024
#define H 16
#define D 64
#define BT (B*T)
#define SCALE 0.125f

typedef __nv_bfloat16 bf16;

// ---------------- scratch (__device__ globals; no allocs allowed) ----------
__device__ bf16 g_qh[(size_t)BT*C], g_ql[(size_t)BT*C];
__device__ bf16 g_kh[(size_t)BT*C], g_kl[(size_t)BT*C];
__device__ bf16 g_vh[(size_t)BT*C], g_vl[(size_t)BT*C];
__device__ bf16 g_ah[(size_t)BT*C], g_al[(size_t)BT*C];
__device__ bf16 g_xh[(size_t)BT*C], g_xl[(size_t)BT*C];   // pre-split input X
__device__ bf16 g_wh[(size_t)C*C],  g_wl[(size_t)C*C];    // pre-split weight

// ---------------- helpers ---------------------------------------------------
__device__ __forceinline__ uint32_t smem_u32(const void* p) {
    uint32_t a;
    asm("{ .reg .u64 t; cvta.to.shared.u64 t, %1; cvt.u32.u64 %0, t; }" : "=r"(a) : "l"(p));
    return a;
}
__device__ __forceinline__ void ldsm4(uint32_t a, uint32_t r[4]) {
    asm volatile("ldmatrix.sync.aligned.m8n8.x4.shared.b16 {%0,%1,%2,%3}, [%4];"
                 : "=r"(r[0]), "=r"(r[1]), "=r"(r[2]), "=r"(r[3]) : "r"(a));
}
__device__ __forceinline__ void ldsm2(uint32_t a, uint32_t r[2]) {
    asm volatile("ldmatrix.sync.aligned.m8n8.x2.shared.b16 {%0,%1}, [%2];"
                 : "=r"(r[0]), "=r"(r[1]) : "r"(a));
}
__device__ __forceinline__ void ldsm2t(uint32_t a, uint32_t r[2]) {
    asm volatile("ldmatrix.sync.aligned.m8n8.x2.trans.shared.b16 {%0,%1}, [%2];"
                 : "=r"(r[0]), "=r"(r[1]) : "r"(a));
}
__device__ __forceinline__ void mma_bf16(float c[4], const uint32_t a[4], const uint32_t b2[2]) {
    asm volatile("mma.sync.aligned.m16n8k16.row.col.f32.bf16.bf16.f32 "
                 "{%0,%1,%2,%3}, {%4,%5,%6,%7}, {%8,%9}, {%0,%1,%2,%3};"
                 : "+f"(c[0]), "+f"(c[1]), "+f"(c[2]), "+f"(c[3])
                 : "r"(a[0]), "r"(a[1]), "r"(a[2]), "r"(a[3]), "r"(b2[0]), "r"(b2[1]));
}
__device__ __forceinline__ uint32_t pack2(bf16 a, bf16 b) {
    __nv_bfloat162 t = __halves2bfloat162(a, b);
    return *(uint32_t*)&t;
}
__device__ __forceinline__ void fsplit(float v, bf16& h, bf16& l) {
    h = __float2bfloat16(v);
    l = __float2bfloat16(v - __bfloat162float(h));
}
__device__ __forceinline__ void cp16(const bf16* s, bf16* d) {
    *(uint4*)d = *(const uint4*)s; *(uint4*)(d + 8) = *(const uint4*)(s + 8);
}

// ---------------------------------------------------------------------------
// Split fp32 -> bf16 hi/lo, 4-wide streaming.
// ---------------------------------------------------------------------------
__global__ void split4(const float4* __restrict__ x, uint2* __restrict__ h,
                       uint2* __restrict__ l, int n4) {
    for (int i = blockIdx.x * blockDim.x + threadIdx.x; i < n4; i += gridDim.x * blockDim.x) {
        float4 v = x[i];
        bf16 h0,h1,h2,h3,l0,l1,l2,l3;
        fsplit(v.x,h0,l0); fsplit(v.y,h1,l1); fsplit(v.z,h2,l2); fsplit(v.w,h3,l3);
        h[i] = make_uint2(pack2(h0,h1), pack2(h2,h3));
        l[i] = make_uint2(pack2(l0,l1), pack2(l2,l3));
    }
}

// ---------------------------------------------------------------------------
// Projection GEMM (pre-split inputs): out = (X @ W^T + bias) * scale
// OUTF32=0: write split bf16; OUTF32=1: write fp32.
// ---------------------------------------------------------------------------
#define PROJ_SMEM (8 * 5120 * 2)

template<int OUTF32>
__global__ __launch_bounds__(256, 2)
void proj_tc(const bf16* __restrict__ Xh, const bf16* __restrict__ Xl,
             const bf16* __restrict__ Wh, const bf16* __restrict__ Wl,
             const float* __restrict__ bias, float scale,
             float* __restrict__ outf, bf16* __restrict__ outh, bf16* __restrict__ outl) {
    extern __shared__ char smc[];
    bf16* sAh = (bf16*)smc;          // [2][128*40]
    bf16* sAl = sAh + 2 * 5120;
    bf16* sBh = sAl + 2 * 5120;
    bf16* sBl = sBh + 2 * 5120;

    const int tid = threadIdx.x;
    const int wid = tid >> 5, lane = tid & 31;
    const int bm = blockIdx.y * 128, bn = blockIdx.x * 128;
    const int wm = (wid >> 2) * 64, wn = (wid & 3) * 32;
    const int srow = tid >> 1, scb = (tid & 1) * 16;

    const bf16* xhp = Xh + (size_t)(bm + srow) * C + scb;
    const bf16* xlp = Xl + (size_t)(bm + srow) * C + scb;
    const bf16* whp = Wh + (size_t)(bn + srow) * C + scb;
    const bf16* wlp = Wl + (size_t)(bn + srow) * C + scb;
    bf16* dAh = sAh + srow * 40 + scb;
    bf16* dAl = sAl + srow * 40 + scb;
    bf16* dBh = sBh + srow * 40 + scb;
    bf16* dBl = sBl + srow * 40 + scb;

    float acc[4][4][4] = {};

    cp16(xhp, dAh); cp16(xlp, dAl); cp16(whp, dBh); cp16(wlp, dBl);
    __syncthreads();

    for (int c = 0; c < 32; c++) {
        const int buf = c & 1;
        if (c + 1 < 32) {
            const int k0 = (c + 1) * 32;
            const int nb = (buf ^ 1) * 5120;
            cp16(xhp + k0, dAh + nb); cp16(xlp + k0, dAl + nb);
            cp16(whp + k0, dBh + nb); cp16(wlp + k0, dBl + nb);
        }
        const uint32_t bAh = smem_u32(sAh + buf * 5120);
        const uint32_t bAl = smem_u32(sAl + buf * 5120);
        const uint32_t bBh = smem_u32(sBh + buf * 5120);
        const uint32_t bBl = smem_u32(sBl + buf * 5120);
#pragma unroll
        for (int s = 0; s < 2; s++) {
            uint32_t afh[4][4], afl[4][4], fbh[4][2], fbl[4][2];
#pragma unroll
            for (int mf = 0; mf < 4; mf++) {
                uint32_t off = (uint32_t)(wm + mf * 16 + (lane & 15)) * 80 + s * 32 + ((lane >> 4) * 16);
                ldsm4(bAh + off, afh[mf]);
                ldsm4(bAl + off, afl[mf]);
            }
#pragma unroll
            for (int nf = 0; nf < 4; nf++) {
                uint32_t off = (uint32_t)(wn + nf * 8 + (lane & 7)) * 80 + s * 32 + (((lane >> 3) & 1) * 16);
                ldsm2(bBh + off, fbh[nf]);
                ldsm2(bBl + off, fbl[nf]);
            }
#pragma unroll
            for (int mf = 0; mf < 4; mf++)
#pragma unroll
                for (int nf = 0; nf < 4; nf++) {
                    mma_bf16(acc[mf][nf], afh[mf], fbh[nf]);
                    mma_bf16(acc[mf][nf], afh[mf], fbl[nf]);
                    mma_bf16(acc[mf][nf], afl[mf], fbh[nf]);
                }
        }
        __syncthreads();
    }

#pragma unroll
    for (int mf = 0; mf < 4; mf++) {
        const int gr = bm + wm + mf * 16 + (lane >> 2);
#pragma unroll
        for (int nf = 0; nf < 4; nf++) {
            const int gc = bn + wn + nf * 8 + (lane & 3) * 2;
            float b0 = bias[gc], b1 = bias[gc + 1];
            float v0 = (acc[mf][nf][0] + b0) * scale;
            float v1 = (acc[mf][nf][1] + b1) * scale;
            float v2 = (acc[mf][nf][2] + b0) * scale;
            float v3 = (acc[mf][nf][3] + b1) * scale;
            if (OUTF32) {
                *(float2*)(outf + (size_t)gr * C + gc)       = make_float2(v0, v1);
                *(float2*)(outf + (size_t)(gr + 8) * C + gc) = make_float2(v2, v3);
            } else {
                bf16 h0,h1,l0,l1; fsplit(v0,h0,l0); fsplit(v1,h1,l1);
                *(uint32_t*)(outh + (size_t)gr * C + gc) = pack2(h0, h1);
                *(uint32_t*)(outl + (size_t)gr * C + gc) = pack2(l0, l1);
                fsplit(v2,h0,l0); fsplit(v3,h1,l1);
                *(uint32_t*)(outh + (size_t)(gr + 8) * C + gc) = pack2(h0, h1);
                *(uint32_t*)(outl + (size_t)(gr + 8) * C + gc) = pack2(l0, l1);
            }
        }
    }
}

// ---------------------------------------------------------------------------
// Fused attention: per (qt, bh) CTA.
//   loop 32-key slabs: S = Q.K^T -> e = masked exp -> write e to attn,
//   split e into SMEM, O += P.V ; row sums in regs.
//   Epilogue: inv = 1/rowsum -> normalized split-bf16 O out;
//   phase 2 re-reads own e rows (L2-hot), writes p = e*inv, zero-fills upper.
// SMEM layout (bf16 elems): Qh 0, Ql 9216 (128x72 each);
//   KV stages at 18432 + stg*9216: Kh 0 / Kl 2304 / Vh 4608 / Vl 6912 (32x72);
//   Ph 36864, Pl 41984 (128x40). Total 47104 elems = 94208 B.
// ---------------------------------------------------------------------------
#define FUSED_SMEM (47104 * 2)

__global__ __launch_bounds__(256, 2)
void attn_fused(const bf16* __restrict__ qh, const bf16* __restrict__ ql,
                const bf16* __restrict__ kh, const bf16* __restrict__ kl,
                const bf16* __restrict__ vh, const bf16* __restrict__ vl,
                const unsigned char* __restrict__ kp,
                float* __restrict__ attn,
                bf16* __restrict__ outh, bf16* __restrict__ outl) {
    const int qt = gridDim.x - 1 - blockIdx.x;   // long CTAs first
    const int bh = blockIdx.y, b = bh >> 4, h = bh & 15;
    extern __shared__ char smc[];
    bf16* S = (bf16*)smc;
    __shared__ float sinv[128];

    const int tid = threadIdx.x, wid = tid >> 5, lane = tid & 31;
    const int wm = (wid >> 2) * 64, wn_o = (wid & 3) * 16;   // O warp layout (2m x 4n)
    const int nkt = 4 * qt + 4;

    // ---- load Q tile (128 x 64, hi+lo) into SMEM ----
    {
        const int r = tid >> 1, c0 = (tid & 1) * 32;
        const size_t off = (size_t)(b * T + qt * 128 + r) * C + h * 64 + c0;
        bf16* d0 = S + r * 72 + c0;
        bf16* d1 = S + 9216 + r * 72 + c0;
#pragma unroll
        for (int j = 0; j < 32; j += 8) {
            *(uint4*)(d0 + j) = *(const uint4*)(qh + off + j);
            *(uint4*)(d1 + j) = *(const uint4*)(ql + off + j);
        }
    }
    const int krow = tid >> 3, kcol = (tid & 7) * 8;
    auto stageKV = [&](int kt, int stg) {
        const size_t go = (size_t)(b * T + kt * 32 + krow) * C + h * 64 + kcol;
        bf16* d = S + 18432 + stg * 9216 + krow * 72 + kcol;
        *(uint4*)(d)        = *(const uint4*)(kh + go);
        *(uint4*)(d + 2304) = *(const uint4*)(kl + go);
        *(uint4*)(d + 4608) = *(const uint4*)(vh + go);
        *(uint4*)(d + 6912) = *(const uint4*)(vl + go);
    };
    stageKV(0, 0);
    __syncthreads();

    float acc_o[4][2][4] = {};
    float rs0 = 0.f, rs1 = 0.f;
    const int lr0 = wid * 16 + (lane >> 2);      // S warp layout (all-m, 16x32)
    const int gr0 = qt * 128 + lr0, gr1 = gr0 + 8;
    float* ab = attn + (size_t)bh * T * T;
    const uint32_t bQh = smem_u32(S), bQl = bQh + 9216 * 2;
    const uint32_t bPh = smem_u32(S + 36864), bPl = bPh + 5120 * 2;

    for (int kt = 0; kt < nkt; kt++) {
        const int stg = kt & 1;
        if (kt + 1 < nkt) stageKV(kt + 1, stg ^ 1);
        const uint32_t bKh = smem_u32(S + 18432) + stg * 9216 * 2;
        const uint32_t bKl = bKh + 2304 * 2;
        const uint32_t bVh = bKh + 4608 * 2;
        const uint32_t bVl = bKh + 6912 * 2;

        // ---- S = Q . K^T ----
        float acc_s[4][4] = {};
#pragma unroll
        for (int ks = 0; ks < 4; ks++) {
            uint32_t ah4[4], al4[4];
            const uint32_t qoff = (uint32_t)(wid * 16 + (lane & 15)) * 144 + ks * 32 + ((lane >> 4) * 16);
            ldsm4(bQh + qoff, ah4);
            ldsm4(bQl + qoff, al4);
#pragma unroll
            for (int nf = 0; nf < 4; nf++) {
                uint32_t kb[2], klb[2];
                const uint32_t koff = (uint32_t)(nf * 8 + (lane & 7)) * 144 + ks * 32 + (((lane >> 3) & 1) * 16);
                ldsm2(bKh + koff, kb);
                ldsm2(bKl + koff, klb);
                mma_bf16(acc_s[nf], ah4, kb);
                mma_bf16(acc_s[nf], ah4, klb);
                mma_bf16(acc_s[nf], al4, kb);
            }
        }
        // ---- exp + mask + write e + split into P SMEM ----
#pragma unroll
        for (int nf = 0; nf < 4; nf++) {
            const int lc = nf * 8 + (lane & 3) * 2;
            const int gc = kt * 32 + lc;
            const float m0 = kp[b * T + gc]     ? 0.f : 1.f;
            const float m1 = kp[b * T + gc + 1] ? 0.f : 1.f;
            float e0 = (gc     <= gr0) ? m0 * __expf(acc_s[nf][0]) : 0.f;
            float e1 = (gc + 1 <= gr0) ? m1 * __expf(acc_s[nf][1]) : 0.f;
            float e2 = (gc     <= gr1) ? m0 * __expf(acc_s[nf][2]) : 0.f;
            float e3 = (gc + 1 <= gr1) ? m1 * __expf(acc_s[nf][3]) : 0.f;
            rs0 += e0 + e1; rs1 += e2 + e3;
            *(float2*)(ab + (size_t)gr0 * T + gc) = make_float2(e0, e1);
            *(float2*)(ab + (size_t)gr1 * T + gc) = make_float2(e2, e3);
            bf16 h0, h1, l0, l1;
            fsplit(e0, h0, l0); fsplit(e1, h1, l1);
            *(uint32_t*)(S + 36864 + lr0 * 40 + lc) = pack2(h0, h1);
            *(uint32_t*)(S + 41984 + lr0 * 40 + lc) = pack2(l0, l1);
            fsplit(e2, h0, l0); fsplit(e3, h1, l1);
            *(uint32_t*)(S + 36864 + (lr0 + 8) * 40 + lc) = pack2(h0, h1);
            *(uint32_t*)(S + 41984 + (lr0 + 8) * 40 + lc) = pack2(l0, l1);
        }
        __syncthreads();

        // ---- O += P . V ----
#pragma unroll
        for (int ks = 0; ks < 2; ks++) {
            uint32_t ph4[4][4], pl4[4][4], vb[2][2], vlb[2][2];
#pragma unroll
            for (int mf = 0; mf < 4; mf++) {
                const uint32_t poff = (uint32_t)(wm + mf * 16 + (lane & 15)) * 80 + ks * 32 + ((lane >> 4) * 16);
                ldsm4(bPh + poff, ph4[mf]);
                ldsm4(bPl + poff, pl4[mf]);
            }
#pragma unroll
            for (int nf = 0; nf < 2; nf++) {
                const uint32_t voff = (uint32_t)(ks * 16 + (lane & 15)) * 144 + (wn_o + nf * 8) * 2;
                ldsm2t(bVh + voff, vb[nf]);
                ldsm2t(bVl + voff, vlb[nf]);
            }
#pragma unroll
            for (int mf = 0; mf < 4; mf++)
#pragma unroll
                for (int nf = 0; nf < 2; nf++) {
                    mma_bf16(acc_o[mf][nf], ph4[mf], vb[nf]);
                    mma_bf16(acc_o[mf][nf], ph4[mf], vlb[nf]);
                    mma_bf16(acc_o[mf][nf], pl4[mf], vb[nf]);
                }
        }
        __syncthreads();
    }

    // ---- row sums -> sinv (each row owned by exactly one warp) ----
    rs0 += __shfl_xor_sync(0xffffffff, rs0, 1);
    rs0 += __shfl_xor_sync(0xffffffff, rs0, 2);
    rs1 += __shfl_xor_sync(0xffffffff, rs1, 1);
    rs1 += __shfl_xor_sync(0xffffffff, rs1, 2);
    if ((lane & 3) == 0) {
        sinv[lr0]     = 1.0f / rs0;
        sinv[lr0 + 8] = 1.0f / rs1;
    }
    __syncthreads();

    // ---- O epilogue: normalize + split bf16 out ----
#pragma unroll
    for (int mf = 0; mf < 4; mf++) {
        const int lrr = wm + mf * 16 + (lane >> 2);
        const float inv0 = sinv[lrr], inv1 = sinv[lrr + 8];
        const int gr = b * T + qt * 128 + lrr;
#pragma unroll
        for (int nf = 0; nf < 2; nf++) {
            const int gc = h * 64 + wn_o + nf * 8 + (lane & 3) * 2;
            bf16 h0, h1, l0, l1;
            fsplit(acc_o[mf][nf][0] * inv0, h0, l0); fsplit(acc_o[mf][nf][1] * inv0, h1, l1);
            *(uint32_t*)(outh + (size_t)gr * C + gc) = pack2(h0, h1);
            *(uint32_t*)(outl + (size_t)gr * C + gc) = pack2(l0, l1);
            fsplit(acc_o[mf][nf][2] * inv1, h0, l0); fsplit(acc_o[mf][nf][3] * inv1, h1, l1);
            *(uint32_t*)(outh + (size_t)(gr + 8) * C + gc) = pack2(h0, h1);
            *(uint32_t*)(outl + (size_t)(gr + 8) * C + gc) = pack2(l0, l1);
        }
    }

    // ---- phase 2: e -> p in place (L2-hot), zero-fill upper region ----
    {
        const int prow = tid >> 1, pcb = (tid & 1) * 16;
        const float pinv = sinv[prow];
        float* arow = ab + (size_t)(qt * 128 + prow) * T + pcb;
        const int lim = nkt * 32;
        for (int c0 = 0; c0 < lim; c0 += 32) {
#pragma unroll
            for (int j = 0; j < 16; j += 4) {
                float4 v = *(float4*)(arow + c0 + j);
                v.x *= pinv; v.y *= pinv; v.z *= pinv; v.w *= pinv;
                *(float4*)(arow + c0 + j) = v;
            }
        }
        const float4 z = {0.f, 0.f, 0.f, 0.f};
        for (int c0 = lim; c0 < T; c0 += 32) {
#pragma unroll
            for (int j = 0; j < 16; j += 4) *(float4*)(arow + c0 + j) = z;
        }
    }
}

// ---------------------------------------------------------------------------
extern "C" void kernel_launch(void* const* d_in, const int* in_sizes, int n_in,
                              void* d_out, int out_size) {
    const float* query = (const float*)d_in[0];
    const float* key   = (const float*)d_in[1];
    const float* value = (const float*)d_in[2];
    const unsigned char* kp = (const unsigned char*)d_in[4];
    const float* Wq = (const float*)d_in[5];  const float* bq = (const float*)d_in[6];
    const float* Wk = (const float*)d_in[7];  const float* bk = (const float*)d_in[8];
    const float* Wv = (const float*)d_in[9];  const float* bv = (const float*)d_in[10];
    const float* Wo = (const float*)d_in[11]; const float* bo = (const float*)d_in[12];

    float* y    = (float*)d_out;
    float* attn = y + (size_t)BT * C;   // tuple order: (y, attn_weights)

    bf16 *qh,*ql,*kh,*kl,*vh,*vl,*ah,*al,*xh,*xl,*wh,*wl;
    cudaGetSymbolAddress((void**)&qh, g_qh); cudaGetSymbolAddress((void**)&ql, g_ql);
    cudaGetSymbolAddress((void**)&kh, g_kh); cudaGetSymbolAddress((void**)&kl, g_kl);
    cudaGetSymbolAddress((void**)&vh, g_vh); cudaGetSymbolAddress((void**)&vl, g_vl);
    cudaGetSymbolAddress((void**)&ah, g_ah); cudaGetSymbolAddress((void**)&al, g_al);
    cudaGetSymbolAddress((void**)&xh, g_xh); cudaGetSymbolAddress((void**)&xl, g_xl);
    cudaGetSymbolAddress((void**)&wh, g_wh); cudaGetSymbolAddress((void**)&wl, g_wl);

    cudaFuncSetAttribute(proj_tc<0>, cudaFuncAttributeMaxDynamicSharedMemorySize, PROJ_SMEM);
    cudaFuncSetAttribute(proj_tc<1>, cudaFuncAttributeMaxDynamicSharedMemorySize, PROJ_SMEM);
    cudaFuncSetAttribute(attn_fused, cudaFuncAttributeMaxDynamicSharedMemorySize, FUSED_SMEM);

    const int nX4 = (BT * C) / 4;
    const int nW4 = (C * C) / 4;
    dim3 pg(C / 128, BT / 128);   // (8, 64)

    // Q projection
    split4<<<2048, 256>>>((const float4*)query, (uint2*)xh, (uint2*)xl, nX4);
    split4<<<512,  256>>>((const float4*)Wq,    (uint2*)wh, (uint2*)wl, nW4);
    proj_tc<0><<<pg, 256, PROJ_SMEM>>>(xh, xl, wh, wl, bq, SCALE, nullptr, qh, ql);
    // K projection
    split4<<<2048, 256>>>((const float4*)key, (uint2*)xh, (uint2*)xl, nX4);
    split4<<<512,  256>>>((const float4*)Wk,  (uint2*)wh, (uint2*)wl, nW4);
    proj_tc<0><<<pg, 256, PROJ_SMEM>>>(xh, xl, wh, wl, bk, 1.0f, nullptr, kh, kl);
    // V projection
    split4<<<2048, 256>>>((const float4*)value, (uint2*)xh, (uint2*)xl, nX4);
    split4<<<512,  256>>>((const float4*)Wv,    (uint2*)wh, (uint2*)wl, nW4);
    proj_tc<0><<<pg, 256, PROJ_SMEM>>>(xh, xl, wh, wl, bv, 1.0f, nullptr, vh, vl);

    // fused attention: scores + exp + AV + normalize + zero-fill
    dim3 fg(T / 128, B * H);   // (16, 64)
    attn_fused<<<fg, 256, FUSED_SMEM>>>(qh, ql, kh, kl, vh, vl, kp, attn, ah, al);

    // output projection
    split4<<<512, 256>>>((const float4*)Wo, (uint2*)wh, (uint2*)wl, nW4);
    proj_tc<1><<<pg, 256, PROJ_SMEM>>>(ah, al, wh, wl, bo, 1.0f, y, nullptr, nullptr);
}

// round 11
// speedup vs baseline: 1.0896x; 1.0896x over previous
#include <cuda_runtime.h>
#include <cuda_bf16.h>
#include <math.h>
#include <stdint.h>

#define B 4
#define T 2048
#define C 1024
#define H 16
#define D 64
#define BT (B*T)
#define SCALE 0.125f

typedef __nv_bfloat16 bf16;

// ---------------- scratch (__device__ globals; no allocs allowed) ----------
__device__ bf16 g_qh[(size_t)BT*C], g_ql[(size_t)BT*C];
__device__ bf16 g_kh[(size_t)BT*C], g_kl[(size_t)BT*C];
__device__ bf16 g_vh[(size_t)BT*C], g_vl[(size_t)BT*C];
__device__ bf16 g_ah[(size_t)BT*C], g_al[(size_t)BT*C];
__device__ bf16 g_ixh[3][(size_t)BT*C], g_ixl[3][(size_t)BT*C];  // split q/k/v inputs
__device__ bf16 g_wsh[4][(size_t)C*C],  g_wsl[4][(size_t)C*C];   // split Wq/Wk/Wv/Wo
__device__ float g_psum[(size_t)B*H*T*16];

// ---------------- helpers ---------------------------------------------------
__device__ __forceinline__ uint32_t smem_u32(const void* p) {
    uint32_t a;
    asm("{ .reg .u64 t; cvta.to.shared.u64 t, %1; cvt.u32.u64 %0, t; }" : "=r"(a) : "l"(p));
    return a;
}
__device__ __forceinline__ void ldsm4(uint32_t a, uint32_t r[4]) {
    asm volatile("ldmatrix.sync.aligned.m8n8.x4.shared.b16 {%0,%1,%2,%3}, [%4];"
                 : "=r"(r[0]), "=r"(r[1]), "=r"(r[2]), "=r"(r[3]) : "r"(a));
}
__device__ __forceinline__ void ldsm2(uint32_t a, uint32_t r[2]) {
    asm volatile("ldmatrix.sync.aligned.m8n8.x2.shared.b16 {%0,%1}, [%2];"
                 : "=r"(r[0]), "=r"(r[1]) : "r"(a));
}
__device__ __forceinline__ void ldsm2t(uint32_t a, uint32_t r[2]) {
    asm volatile("ldmatrix.sync.aligned.m8n8.x2.trans.shared.b16 {%0,%1}, [%2];"
                 : "=r"(r[0]), "=r"(r[1]) : "r"(a));
}
__device__ __forceinline__ void mma_bf16(float c[4], const uint32_t a[4], const uint32_t b2[2]) {
    asm volatile("mma.sync.aligned.m16n8k16.row.col.f32.bf16.bf16.f32 "
                 "{%0,%1,%2,%3}, {%4,%5,%6,%7}, {%8,%9}, {%0,%1,%2,%3};"
                 : "+f"(c[0]), "+f"(c[1]), "+f"(c[2]), "+f"(c[3])
                 : "r"(a[0]), "r"(a[1]), "r"(a[2]), "r"(a[3]), "r"(b2[0]), "r"(b2[1]));
}
__device__ __forceinline__ uint32_t pack2(bf16 a, bf16 b) {
    __nv_bfloat162 t = __halves2bfloat162(a, b);
    return *(uint32_t*)&t;
}
__device__ __forceinline__ void fsplit(float v, bf16& h, bf16& l) {
    h = __float2bfloat16(v);
    l = __float2bfloat16(v - __bfloat162float(h));
}
__device__ __forceinline__ void cp16(const bf16* s, bf16* d) {
    *(uint4*)d = *(const uint4*)s; *(uint4*)(d + 8) = *(const uint4*)(s + 8);
}
// stage 16 probs: read e, normalize, write p back to global, split into smem
__device__ __forceinline__ void stage16_norm(float* gptr, float inv, bf16* dh, bf16* dl) {
#pragma unroll
    for (int j = 0; j < 16; j += 4) {
        float4 v = *(const float4*)(gptr + j);
        v.x *= inv; v.y *= inv; v.z *= inv; v.w *= inv;
        *(float4*)(gptr + j) = v;
        bf16 h0,h1,h2,h3,l0,l1,l2,l3;
        fsplit(v.x,h0,l0); fsplit(v.y,h1,l1); fsplit(v.z,h2,l2); fsplit(v.w,h3,l3);
        *(uint2*)(dh + j) = make_uint2(pack2(h0,h1), pack2(h2,h3));
        *(uint2*)(dl + j) = make_uint2(pack2(l0,l1), pack2(l2,l3));
    }
}

// ---------------------------------------------------------------------------
// split_all: one launch splits all 7 fp32 tensors to bf16 hi/lo.
// ---------------------------------------------------------------------------
struct SplitArgs {
    const float4* src[7];
    uint2* dh[7];
    uint2* dl[7];
    int n4[7];
};
__global__ void split_all(SplitArgs a) {
    const int t = blockIdx.y;
    const float4* __restrict__ x = a.src[t];
    uint2* __restrict__ h = a.dh[t];
    uint2* __restrict__ l = a.dl[t];
    const int n4 = a.n4[t];
    for (int i = blockIdx.x * blockDim.x + threadIdx.x; i < n4; i += gridDim.x * blockDim.x) {
        float4 v = x[i];
        bf16 h0,h1,h2,h3,l0,l1,l2,l3;
        fsplit(v.x,h0,l0); fsplit(v.y,h1,l1); fsplit(v.z,h2,l2); fsplit(v.w,h3,l3);
        h[i] = make_uint2(pack2(h0,h1), pack2(h2,h3));
        l[i] = make_uint2(pack2(l0,l1), pack2(l2,l3));
    }
}

// ---------------------------------------------------------------------------
// Projection GEMM body (pre-split inputs): out = (X @ W^T + bias) * scale
// 128x128 tile, BK=32, 256 thr, double-buffered, pure-copy staging.
// ---------------------------------------------------------------------------
#define PROJ_SMEM (8 * 5120 * 2)

template<int OUTF32>
__device__ __forceinline__ void proj_body(
    const bf16* __restrict__ Xh, const bf16* __restrict__ Xl,
    const bf16* __restrict__ Wh, const bf16* __restrict__ Wl,
    const float* __restrict__ bias, float scale,
    float* __restrict__ outf, bf16* __restrict__ outh, bf16* __restrict__ outl,
    char* smc, int bm, int bn) {
    bf16* sAh = (bf16*)smc;          // [2][128*40]
    bf16* sAl = sAh + 2 * 5120;
    bf16* sBh = sAl + 2 * 5120;
    bf16* sBl = sBh + 2 * 5120;

    const int tid = threadIdx.x;
    const int wid = tid >> 5, lane = tid & 31;
    const int wm = (wid >> 2) * 64, wn = (wid & 3) * 32;
    const int srow = tid >> 1, scb = (tid & 1) * 16;

    const bf16* xhp = Xh + (size_t)(bm + srow) * C + scb;
    const bf16* xlp = Xl + (size_t)(bm + srow) * C + scb;
    const bf16* whp = Wh + (size_t)(bn + srow) * C + scb;
    const bf16* wlp = Wl + (size_t)(bn + srow) * C + scb;
    bf16* dAh = sAh + srow * 40 + scb;
    bf16* dAl = sAl + srow * 40 + scb;
    bf16* dBh = sBh + srow * 40 + scb;
    bf16* dBl = sBl + srow * 40 + scb;

    float acc[4][4][4] = {};

    cp16(xhp, dAh); cp16(xlp, dAl); cp16(whp, dBh); cp16(wlp, dBl);
    __syncthreads();

    for (int c = 0; c < 32; c++) {
        const int buf = c & 1;
        if (c + 1 < 32) {
            const int k0 = (c + 1) * 32;
            const int nb = (buf ^ 1) * 5120;
            cp16(xhp + k0, dAh + nb); cp16(xlp + k0, dAl + nb);
            cp16(whp + k0, dBh + nb); cp16(wlp + k0, dBl + nb);
        }
        const uint32_t bAh = smem_u32(sAh + buf * 5120);
        const uint32_t bAl = smem_u32(sAl + buf * 5120);
        const uint32_t bBh = smem_u32(sBh + buf * 5120);
        const uint32_t bBl = smem_u32(sBl + buf * 5120);
#pragma unroll
        for (int s = 0; s < 2; s++) {
            uint32_t afh[4][4], afl[4][4], fbh[4][2], fbl[4][2];
#pragma unroll
            for (int mf = 0; mf < 4; mf++) {
                uint32_t off = (uint32_t)(wm + mf * 16 + (lane & 15)) * 80 + s * 32 + ((lane >> 4) * 16);
                ldsm4(bAh + off, afh[mf]);
                ldsm4(bAl + off, afl[mf]);
            }
#pragma unroll
            for (int nf = 0; nf < 4; nf++) {
                uint32_t off = (uint32_t)(wn + nf * 8 + (lane & 7)) * 80 + s * 32 + (((lane >> 3) & 1) * 16);
                ldsm2(bBh + off, fbh[nf]);
                ldsm2(bBl + off, fbl[nf]);
            }
#pragma unroll
            for (int mf = 0; mf < 4; mf++)
#pragma unroll
                for (int nf = 0; nf < 4; nf++) {
                    mma_bf16(acc[mf][nf], afh[mf], fbh[nf]);
                    mma_bf16(acc[mf][nf], afh[mf], fbl[nf]);
                    mma_bf16(acc[mf][nf], afl[mf], fbh[nf]);
                }
        }
        __syncthreads();
    }

#pragma unroll
    for (int mf = 0; mf < 4; mf++) {
        const int gr = bm + wm + mf * 16 + (lane >> 2);
#pragma unroll
        for (int nf = 0; nf < 4; nf++) {
            const int gc = bn + wn + nf * 8 + (lane & 3) * 2;
            float b0 = bias[gc], b1 = bias[gc + 1];
            float v0 = (acc[mf][nf][0] + b0) * scale;
            float v1 = (acc[mf][nf][1] + b1) * scale;
            float v2 = (acc[mf][nf][2] + b0) * scale;
            float v3 = (acc[mf][nf][3] + b1) * scale;
            if (OUTF32) {
                *(float2*)(outf + (size_t)gr * C + gc)       = make_float2(v0, v1);
                *(float2*)(outf + (size_t)(gr + 8) * C + gc) = make_float2(v2, v3);
            } else {
                bf16 h0,h1,l0,l1; fsplit(v0,h0,l0); fsplit(v1,h1,l1);
                *(uint32_t*)(outh + (size_t)gr * C + gc) = pack2(h0, h1);
                *(uint32_t*)(outl + (size_t)gr * C + gc) = pack2(l0, l1);
                fsplit(v2,h0,l0); fsplit(v3,h1,l1);
                *(uint32_t*)(outh + (size_t)(gr + 8) * C + gc) = pack2(h0, h1);
                *(uint32_t*)(outl + (size_t)(gr + 8) * C + gc) = pack2(l0, l1);
            }
        }
    }
}

// ---------------------------------------------------------------------------
// qkvz: merged Q-proj / K-proj / V-proj / zero-fill in one launch.
// grid (32, 64): role z = bx & 3 (fastest-varying -> roles interleave),
// nx = bx >> 2. z<3: projection; z==3: zero strictly-upper attn region.
// ---------------------------------------------------------------------------
struct QkvArgs {
    const bf16 *xh[3], *xl[3];
    const bf16 *wh[3], *wl[3];
    const float *bias[3];
    bf16 *oh[3], *ol[3];
    float* attn;
};

__global__ __launch_bounds__(256, 2)
void qkvz(QkvArgs a) {
    extern __shared__ char smc[];
    const int z = blockIdx.x & 3;
    const int nx = blockIdx.x >> 2;
    if (z < 3) {
        const float scale = (z == 0) ? SCALE : 1.0f;
        proj_body<0>(a.xh[z], a.xl[z], a.wh[z], a.wl[z], a.bias[z], scale,
                     nullptr, a.oh[z], a.ol[z], smc, blockIdx.y * 128, nx * 128);
    } else {
        // zero-fill: units u = (bh, qt) with qt < 15; 960 units over 512 blocks
        const int w = nx + blockIdx.y * 8;   // 0..511
        const int tid = threadIdx.x;
        const float4 zv = {0.f, 0.f, 0.f, 0.f};
        for (int u = w; u < 960; u += 512) {
            const int bh = u / 15, qt = u % 15;
            float* base = a.attn + (size_t)bh * T * T + (size_t)(qt * 128) * T + (qt + 1) * 128;
            const int L4 = (T - (qt + 1) * 128) >> 2;   // float4s per row
            const int r = tid >> 1;
            float4* row = (float4*)(base + (size_t)r * T);
            for (int c = (tid & 1); c < L4; c += 2) row[c] = zv;
        }
    }
}

// ---------------------------------------------------------------------------
// proj_tc1: output projection (fp32 out), standalone kernel.
// ---------------------------------------------------------------------------
__global__ __launch_bounds__(256, 2)
void proj_tc1(const bf16* __restrict__ Xh, const bf16* __restrict__ Xl,
              const bf16* __restrict__ Wh, const bf16* __restrict__ Wl,
              const float* __restrict__ bias, float* __restrict__ outf) {
    extern __shared__ char smc[];
    proj_body<1>(Xh, Xl, Wh, Wl, bias, 1.0f, outf, nullptr, nullptr,
                 smc, blockIdx.y * 128, blockIdx.x * 128);
}

// ---------------------------------------------------------------------------
// Scores+exp: e = exp(Q.K^T) masked; writes e to attn, row partial sums to psum.
// Packed triangular grid: 136 tiles per bh.
// ---------------------------------------------------------------------------
#define SCORES_SMEM (4 * 9216 * 2)

__global__ __launch_bounds__(256, 2)
void scores_tc(const bf16* __restrict__ qh, const bf16* __restrict__ ql,
               const bf16* __restrict__ kh, const bf16* __restrict__ kl,
               const unsigned char* __restrict__ kp, float* __restrict__ attn,
               float* __restrict__ psum) {
    // triangular decode: blockIdx.x in [0,136) -> (qt, kt), kt <= qt
    int i = blockIdx.x;
    int qt = (int)((sqrtf(8.f * i + 1.f) - 1.f) * 0.5f);
    if ((qt + 1) * (qt + 2) / 2 <= i) qt++;
    else if (qt * (qt + 1) / 2 > i) qt--;
    const int kt = i - qt * (qt + 1) / 2;
    const int bh = blockIdx.y;
    const int b = bh >> 4, h = bh & 15;

    extern __shared__ char smc[];
    bf16* sQh = (bf16*)smc;          // [128*72]
    bf16* sQl = sQh + 9216;
    bf16* sKh = sQl + 9216;
    bf16* sKl = sKh + 9216;
    __shared__ float sred[4][128];

    const int tid = threadIdx.x;
    const int wid = tid >> 5, lane = tid & 31;
    const int wm = (wid >> 2) * 64, wn = (wid & 3) * 32;
    const int srow = tid >> 1, scb = (tid & 1) * 32;

    {
        const size_t qoff = (size_t)(b * T + qt * 128 + srow) * C + h * 64 + scb;
        const size_t koff = (size_t)(b * T + kt * 128 + srow) * C + h * 64 + scb;
        bf16* d;
        d = sQh + srow * 72 + scb;
#pragma unroll
        for (int j = 0; j < 32; j += 8) *(uint4*)(d + j) = *(const uint4*)(qh + qoff + j);
        d = sQl + srow * 72 + scb;
#pragma unroll
        for (int j = 0; j < 32; j += 8) *(uint4*)(d + j) = *(const uint4*)(ql + qoff + j);
        d = sKh + srow * 72 + scb;
#pragma unroll
        for (int j = 0; j < 32; j += 8) *(uint4*)(d + j) = *(const uint4*)(kh + koff + j);
        d = sKl + srow * 72 + scb;
#pragma unroll
        for (int j = 0; j < 32; j += 8) *(uint4*)(d + j) = *(const uint4*)(kl + koff + j);
    }
    __syncthreads();

    float acc[4][4][4] = {};
    const uint32_t bQh = smem_u32(sQh), bQl = smem_u32(sQl);
    const uint32_t bKh = smem_u32(sKh), bKl = smem_u32(sKl);

#pragma unroll
    for (int s = 0; s < 4; s++) {
        uint32_t afh[4][4], afl[4][4], fbh[4][2], fbl[4][2];
#pragma unroll
        for (int mf = 0; mf < 4; mf++) {
            uint32_t off = (uint32_t)(wm + mf * 16 + (lane & 15)) * 144 + s * 32 + ((lane >> 4) * 16);
            ldsm4(bQh + off, afh[mf]);
            ldsm4(bQl + off, afl[mf]);
        }
#pragma unroll
        for (int nf = 0; nf < 4; nf++) {
            uint32_t off = (uint32_t)(wn + nf * 8 + (lane & 7)) * 144 + s * 32 + (((lane >> 3) & 1) * 16);
            ldsm2(bKh + off, fbh[nf]);
            ldsm2(bKl + off, fbl[nf]);
        }
#pragma unroll
        for (int mf = 0; mf < 4; mf++)
#pragma unroll
            for (int nf = 0; nf < 4; nf++) {
                mma_bf16(acc[mf][nf], afh[mf], fbh[nf]);
                mma_bf16(acc[mf][nf], afh[mf], fbl[nf]);
                mma_bf16(acc[mf][nf], afl[mf], fbh[nf]);
            }
    }

    float kpc[8];
#pragma unroll
    for (int nf = 0; nf < 4; nf++) {
        const int gc = kt * 128 + wn + nf * 8 + (lane & 3) * 2;
        kpc[nf*2]   = kp[b * T + gc]     ? 0.f : 1.f;
        kpc[nf*2+1] = kp[b * T + gc + 1] ? 0.f : 1.f;
    }

    float* ab = attn + (size_t)bh * T * T;
#pragma unroll
    for (int mf = 0; mf < 4; mf++) {
        const int lr0 = wm + mf * 16 + (lane >> 2);
        const int gr0 = qt * 128 + lr0;
        const int gr1 = gr0 + 8;
        float rs0 = 0.f, rs1 = 0.f;
#pragma unroll
        for (int nf = 0; nf < 4; nf++) {
            const int gc = kt * 128 + wn + nf * 8 + (lane & 3) * 2;
            float e0 = (gc     <= gr0) ? kpc[nf*2]   * __expf(acc[mf][nf][0]) : 0.f;
            float e1 = (gc + 1 <= gr0) ? kpc[nf*2+1] * __expf(acc[mf][nf][1]) : 0.f;
            float e2 = (gc     <= gr1) ? kpc[nf*2]   * __expf(acc[mf][nf][2]) : 0.f;
            float e3 = (gc + 1 <= gr1) ? kpc[nf*2+1] * __expf(acc[mf][nf][3]) : 0.f;
            rs0 += e0 + e1; rs1 += e2 + e3;
            *(float2*)(ab + (size_t)gr0 * T + gc) = make_float2(e0, e1);
            *(float2*)(ab + (size_t)gr1 * T + gc) = make_float2(e2, e3);
        }
        rs0 += __shfl_xor_sync(0xffffffff, rs0, 1);
        rs0 += __shfl_xor_sync(0xffffffff, rs0, 2);
        rs1 += __shfl_xor_sync(0xffffffff, rs1, 1);
        rs1 += __shfl_xor_sync(0xffffffff, rs1, 2);
        if ((lane & 3) == 0) {
            sred[wid & 3][lr0]     = rs0;
            sred[wid & 3][lr0 + 8] = rs1;
        }
    }
    __syncthreads();
    if (tid < 128) {
        float s = sred[0][tid] + sred[1][tid] + sred[2][tid] + sred[3][tid];
        psum[((size_t)bh * T + qt * 128 + tid) * 16 + kt] = s;
    }
}

// ---------------------------------------------------------------------------
// AV + normalize (R7 single-buffer body, reversed qt for wave balance).
// ---------------------------------------------------------------------------
#define AV_SMEM ((2 * 5120 + 2 * 2304) * 2)

__global__ __launch_bounds__(256, 2)
void av_tc(float* __restrict__ attn, const float* __restrict__ psum,
           const bf16* __restrict__ vh, const bf16* __restrict__ vl,
           bf16* __restrict__ outh, bf16* __restrict__ outl) {
    const int qt = gridDim.x - 1 - blockIdx.x;   // long CTAs first
    const int bh = blockIdx.y;
    const int b = bh >> 4, h = bh & 15;

    extern __shared__ char smc[];
    bf16* sPh = (bf16*)smc;          // [128*40]
    bf16* sPl = sPh + 5120;
    bf16* sVh = sPl + 5120;          // [32*72]
    bf16* sVl = sVh + 2304;
    __shared__ float sinv[128];

    const int tid = threadIdx.x;
    const int wid = tid >> 5, lane = tid & 31;
    const int wm = (wid >> 2) * 64, wn = (wid & 3) * 16;
    const int prow = tid >> 1, pcb = (tid & 1) * 16;
    const int vrow = tid >> 3, vcb = (tid & 7) * 8;

    if (tid < 128) {
        const float* ps = psum + ((size_t)bh * T + qt * 128 + tid) * 16;
        float s = 0.f;
        for (int k = 0; k <= qt; k++) s += ps[k];
        sinv[tid] = 1.0f / s;
    }
    __syncthreads();

    float acc[4][2][4] = {};
    const int nkt = 4 * qt + 4;
    const float pinv = sinv[prow];

    const uint32_t bPh = smem_u32(sPh), bPl = smem_u32(sPl);
    const uint32_t bVh = smem_u32(sVh), bVl = smem_u32(sVl);

    for (int kt = 0; kt < nkt; kt++) {
        const int t0 = kt * 32;
        stage16_norm(attn + (size_t)bh * T * T + (size_t)(qt * 128 + prow) * T + t0 + pcb,
                     pinv, sPh + prow * 40 + pcb, sPl + prow * 40 + pcb);
        {
            const size_t voff = (size_t)(b * T + t0 + vrow) * C + h * 64 + vcb;
            *(uint4*)(sVh + vrow * 72 + vcb) = *(const uint4*)(vh + voff);
            *(uint4*)(sVl + vrow * 72 + vcb) = *(const uint4*)(vl + voff);
        }
        __syncthreads();

#pragma unroll
        for (int s = 0; s < 2; s++) {
            uint32_t afh[4][4], afl[4][4], fbh[2][2], fbl[2][2];
#pragma unroll
            for (int mf = 0; mf < 4; mf++) {
                uint32_t off = (uint32_t)(wm + mf * 16 + (lane & 15)) * 80 + s * 32 + ((lane >> 4) * 16);
                ldsm4(bPh + off, afh[mf]);
                ldsm4(bPl + off, afl[mf]);
            }
#pragma unroll
            for (int nf = 0; nf < 2; nf++) {
                uint32_t off = (uint32_t)(s * 16 + (lane & 15)) * 144 + (wn + nf * 8) * 2;
                ldsm2t(bVh + off, fbh[nf]);
                ldsm2t(bVl + off, fbl[nf]);
            }
#pragma unroll
            for (int mf = 0; mf < 4; mf++)
#pragma unroll
                for (int nf = 0; nf < 2; nf++) {
                    mma_bf16(acc[mf][nf], afh[mf], fbh[nf]);
                    mma_bf16(acc[mf][nf], afh[mf], fbl[nf]);
                    mma_bf16(acc[mf][nf], afl[mf], fbh[nf]);
                }
        }
        __syncthreads();
    }

#pragma unroll
    for (int mf = 0; mf < 4; mf++) {
        const int gr = b * T + qt * 128 + wm + mf * 16 + (lane >> 2);
#pragma unroll
        for (int nf = 0; nf < 2; nf++) {
            const int gc = h * 64 + wn + nf * 8 + (lane & 3) * 2;
            bf16 h0,h1,l0,l1;
            fsplit(acc[mf][nf][0], h0, l0); fsplit(acc[mf][nf][1], h1, l1);
            *(uint32_t*)(outh + (size_t)gr * C + gc) = pack2(h0, h1);
            *(uint32_t*)(outl + (size_t)gr * C + gc) = pack2(l0, l1);
            fsplit(acc[mf][nf][2], h0, l0); fsplit(acc[mf][nf][3], h1, l1);
            *(uint32_t*)(outh + (size_t)(gr + 8) * C + gc) = pack2(h0, h1);
            *(uint32_t*)(outl + (size_t)(gr + 8) * C + gc) = pack2(l0, l1);
        }
    }
}

// ---------------------------------------------------------------------------
extern "C" void kernel_launch(void* const* d_in, const int* in_sizes, int n_in,
                              void* d_out, int out_size) {
    const float* query = (const float*)d_in[0];
    const float* key   = (const float*)d_in[1];
    const float* value = (const float*)d_in[2];
    const unsigned char* kp = (const unsigned char*)d_in[4];
    const float* Wq = (const float*)d_in[5];  const float* bq = (const float*)d_in[6];
    const float* Wk = (const float*)d_in[7];  const float* bk = (const float*)d_in[8];
    const float* Wv = (const float*)d_in[9];  const float* bv = (const float*)d_in[10];
    const float* Wo = (const float*)d_in[11]; const float* bo = (const float*)d_in[12];

    float* y    = (float*)d_out;
    float* attn = y + (size_t)BT * C;   // tuple order: (y, attn_weights)

    bf16 *qh,*ql,*kh,*kl,*vh,*vl,*ah,*al,*ixh,*ixl,*wsh,*wsl;
    float* psum;
    cudaGetSymbolAddress((void**)&qh, g_qh); cudaGetSymbolAddress((void**)&ql, g_ql);
    cudaGetSymbolAddress((void**)&kh, g_kh); cudaGetSymbolAddress((void**)&kl, g_kl);
    cudaGetSymbolAddress((void**)&vh, g_vh); cudaGetSymbolAddress((void**)&vl, g_vl);
    cudaGetSymbolAddress((void**)&ah, g_ah); cudaGetSymbolAddress((void**)&al, g_al);
    cudaGetSymbolAddress((void**)&ixh, g_ixh); cudaGetSymbolAddress((void**)&ixl, g_ixl);
    cudaGetSymbolAddress((void**)&wsh, g_wsh); cudaGetSymbolAddress((void**)&wsl, g_wsl);
    cudaGetSymbolAddress((void**)&psum, g_psum);

    const size_t NX = (size_t)BT * C;   // input elems
    const size_t NW = (size_t)C * C;    // weight elems

    cudaFuncSetAttribute(qkvz,      cudaFuncAttributeMaxDynamicSharedMemorySize, PROJ_SMEM);
    cudaFuncSetAttribute(proj_tc1,  cudaFuncAttributeMaxDynamicSharedMemorySize, PROJ_SMEM);
    cudaFuncSetAttribute(scores_tc, cudaFuncAttributeMaxDynamicSharedMemorySize, SCORES_SMEM);

    // ---- 1. split all 7 tensors in one launch ----
    SplitArgs sa;
    const float* srcs[7] = {query, key, value, Wq, Wk, Wv, Wo};
    for (int i = 0; i < 3; i++) {
        sa.src[i] = (const float4*)srcs[i];
        sa.dh[i] = (uint2*)(ixh + i * NX);
        sa.dl[i] = (uint2*)(ixl + i * NX);
        sa.n4[i] = (int)(NX / 4);
    }
    for (int i = 0; i < 4; i++) {
        sa.src[3 + i] = (const float4*)srcs[3 + i];
        sa.dh[3 + i] = (uint2*)(wsh + i * NW);
        sa.dl[3 + i] = (uint2*)(wsl + i * NW);
        sa.n4[3 + i] = (int)(NW / 4);
    }
    split_all<<<dim3(512, 7), 256>>>(sa);

    // ---- 2. merged QKV projections + zero-fill ----
    QkvArgs qa;
    bf16* ohs[3] = {qh, kh, vh};
    bf16* ols[3] = {ql, kl, vl};
    const float* biases[3] = {bq, bk, bv};
    for (int i = 0; i < 3; i++) {
        qa.xh[i] = ixh + i * NX;  qa.xl[i] = ixl + i * NX;
        qa.wh[i] = wsh + i * NW;  qa.wl[i] = wsl + i * NW;
        qa.bias[i] = biases[i];
        qa.oh[i] = ohs[i];        qa.ol[i] = ols[i];
    }
    qa.attn = attn;
    qkvz<<<dim3(32, 64), 256, PROJ_SMEM>>>(qa);

    // ---- 3. scores + exp + row partial sums (packed triangular grid) ----
    scores_tc<<<dim3(136, 64), 256, SCORES_SMEM>>>(qh, ql, kh, kl, kp, attn, psum);

    // ---- 4. AV + in-place normalization ----
    av_tc<<<dim3(16, 64), 256, AV_SMEM>>>(attn, psum, vh, vl, ah, al);

    // ---- 5. output projection ----
    proj_tc1<<<dim3(8, 64), 256, PROJ_SMEM>>>(ah, al, wsh + 3 * NW, wsl + 3 * NW, bo, y);
}